// round 7
// baseline (speedup 1.0000x reference)
#include <cuda_runtime.h>
#include <cstdint>

// ExodusNet: per-timestep dense (32 -> 1), ExpLeak scan, LIF scan with
// SingleSpike + MembraneSubtract.  x: (B, 32, 100) fp32 (t innermost),
// w: (32) fp32, out: (B, 100) fp32 of 0/1 spikes.
//
// R7: persistent warp-autonomous pipeline.  Each warp owns a contiguous
// range of ~27 batch rows and runs a private 2-stage cp.async.bulk ring
// (as in the 70.1us R6 kernel).  Scan + writeout happen per 4-row group
// INSIDE the streaming loop, after the next TMA copies are already issued,
// so DMA never drains.  No __syncthreads in the hot loop; no wave tail
// (grid = 2 x SM count, single wave).  FMA / scan orderings bitwise
// identical to the rel_err==0 kernels.

namespace {

constexpr int T_STEPS    = 100;
constexpr int F_DIM      = 32;
constexpr int ROW_FLOATS = F_DIM * T_STEPS;        // 3200 floats per row
constexpr int CHUNK      = ROW_FLOATS * 4;         // 12800 bytes per row
constexpr int THREADS    = 128;                    // 4 warps
constexpr int NSTAGE     = 2;                      // ring depth per warp
constexpr int GROUP      = 4;                      // rows per scan group
constexpr int SM_STRIDE  = 101;                    // conflict-free scan reads

// dynamic smem layout (bytes)
constexpr int WSH_OFF  = 0;                                    // 32 floats
constexpr int MBAR_OFF = 128;                                  // 4 warps * 2 * 8B
constexpr int ISH_OFF  = 192;                                  // 4 warps * 4 rows * 101 floats
constexpr int ISH_BYTES = 4 * GROUP * SM_STRIDE * 4;           // 6464
constexpr int RING_OFF = ISH_OFF + ISH_BYTES;                  // 6656 (16B aligned)
constexpr int SMEM_BYTES = RING_OFF + 4 * NSTAGE * CHUNK;      // 109056

__device__ __forceinline__ float alpha_f() { return (float)0.9048374180359595; }
__device__ __forceinline__ float one_m_a() { return (float)(1.0 - 0.9048374180359595); }

__device__ __forceinline__ uint32_t smem_u32(const void* p) {
    uint32_t a;
    asm("{ .reg .u64 t; cvta.to.shared.u64 t, %1; cvt.u32.u64 %0, t; }"
        : "=r"(a) : "l"(p));
    return a;
}
__device__ __forceinline__ void mbar_init(uint32_t mbar, uint32_t cnt) {
    asm volatile("mbarrier.init.shared.b64 [%0], %1;" :: "r"(mbar), "r"(cnt) : "memory");
}
__device__ __forceinline__ void mbar_expect_tx(uint32_t mbar, uint32_t bytes) {
    asm volatile("mbarrier.arrive.expect_tx.shared.b64 _, [%0], %1;"
                 :: "r"(mbar), "r"(bytes) : "memory");
}
__device__ __forceinline__ void bulk_copy_g2s(uint32_t dst_smem, const void* src_gmem,
                                              uint32_t bytes, uint32_t mbar) {
    asm volatile(
        "cp.async.bulk.shared::cluster.global.mbarrier::complete_tx::bytes "
        "[%0], [%1], %2, [%3];"
        :: "r"(dst_smem), "l"(src_gmem), "r"(bytes), "r"(mbar) : "memory");
}
__device__ __forceinline__ void mbar_wait_parity(uint32_t mbar, uint32_t parity) {
    asm volatile(
        "{\n\t"
        ".reg .pred P1;\n\t"
        "WAIT_LOOP_%=:\n\t"
        "mbarrier.try_wait.parity.acquire.cta.shared::cta.b64 P1, [%0], %1, 0x989680;\n\t"
        "@P1 bra.uni WAIT_DONE_%=;\n\t"
        "bra.uni WAIT_LOOP_%=;\n\t"
        "WAIT_DONE_%=:\n\t"
        "}"
        :: "r"(mbar), "r"(parity) : "memory");
}

__global__ __launch_bounds__(THREADS)
void exodus_kernel(const float* __restrict__ x,
                   const float* __restrict__ w,
                   float* __restrict__ out,
                   int B)
{
    extern __shared__ __align__(16) unsigned char smem_raw[];
    float* wsh = reinterpret_cast<float*>(smem_raw + WSH_OFF);

    const uint32_t smem_base = smem_u32(smem_raw);
    const int tid  = threadIdx.x;
    const int warp = tid >> 5;
    const int lane = tid & 31;

    if (tid < F_DIM) wsh[tid] = w[tid];
    if (tid == 0) {
        #pragma unroll
        for (int m = 0; m < 4 * NSTAGE; ++m)
            mbar_init(smem_base + MBAR_OFF + m * 8, 1);
    }
    __syncthreads();

    // ---- static row range for this warp (contiguous; +/-1 row imbalance) ----
    const int warps_total = gridDim.x * (THREADS / 32);
    const int gw          = blockIdx.x * (THREADS / 32) + warp;
    const int rows_per    = B / warps_total;
    const int rem         = B - rows_per * warps_total;
    const int start       = gw * rows_per + (gw < rem ? gw : rem);
    const int n_rows      = rows_per + (gw < rem ? 1 : 0);

    const uint32_t ring_base = smem_base + RING_OFF + warp * (NSTAGE * CHUNK);
    const uint32_t mbar_base = smem_base + MBAR_OFF + warp * (NSTAGE * 8);
    float* ish_w = reinterpret_cast<float*>(smem_raw + ISH_OFF) +
                   warp * (GROUP * SM_STRIDE);

    // ---- prologue: fill both stages ----
    if (lane == 0) {
        #pragma unroll
        for (int s = 0; s < NSTAGE; ++s) {
            if (s < n_rows) {
                mbar_expect_tx(mbar_base + s * 8, CHUNK);
                bulk_copy_g2s(ring_base + s * CHUNK,
                              x + (size_t)(start + s) * ROW_FLOATS,
                              CHUNK, mbar_base + s * 8);
            }
        }
    }

    // ---- persistent streaming loop ----
    for (int j = 0; j < n_rows; ++j) {
        const int s  = j & 1;
        const int ph = (j >> 1) & 1;
        mbar_wait_parity(mbar_base + s * 8, (uint32_t)ph);

        // consume stage s: weighted currents into ish slot (j&3)
        if (lane < 25) {
            const float* stage = reinterpret_cast<const float*>(
                smem_raw + RING_OFF + warp * (NSTAGE * CHUNK) + s * CHUNK);
            const float* base = stage + 4 * lane;
            float4 acc = make_float4(0.f, 0.f, 0.f, 0.f);
            #pragma unroll
            for (int f = 0; f < F_DIM; ++f) {
                const float4 xa = *reinterpret_cast<const float4*>(base + f * T_STEPS);
                const float wf = wsh[f];
                acc.x = fmaf(xa.x, wf, acc.x);
                acc.y = fmaf(xa.y, wf, acc.y);
                acc.z = fmaf(xa.z, wf, acc.z);
                acc.w = fmaf(xa.w, wf, acc.w);
            }
            float* ip = ish_w + (j & (GROUP - 1)) * SM_STRIDE + 4 * lane;
            ip[0] = acc.x;
            ip[1] = acc.y;
            ip[2] = acc.z;
            ip[3] = acc.w;
        }
        __syncwarp();   // stage fully read; ish slot visible warp-wide

        // keep the DMA engine fed BEFORE any scan/writeout work
        if (lane == 0 && j + NSTAGE < n_rows) {
            mbar_expect_tx(mbar_base + s * 8, CHUNK);
            bulk_copy_g2s(ring_base + s * CHUNK,
                          x + (size_t)(start + j + NSTAGE) * ROW_FLOATS,
                          CHUNK, mbar_base + s * 8);
        }

        // ---- group boundary: scan + writeout (overlapped with in-flight TMA) ----
        if ((j & (GROUP - 1)) == (GROUP - 1) || j == n_rows - 1) {
            const int cnt    = (j & (GROUP - 1)) + 1;
            const int g_row0 = start + (j & ~(GROUP - 1));

            // scan: lane k handles row k of the group (banks 0,5,10,15 -> no conflicts)
            if (lane < cnt) {
                float* ip = ish_w + lane * SM_STRIDE;
                float syn = 0.f, v = 0.f;
                #pragma unroll 4
                for (int t = 0; t < T_STEPS; ++t) {
                    const float i = ip[t];
                    syn = fmaf(alpha_f(), syn, i);
                    v   = fmaf(alpha_f(), v, one_m_a() * syn);
                    const float sp = (v >= 1.0f) ? 1.0f : 0.0f;
                    v -= sp;
                    ip[t] = sp;
                }
            }
            __syncwarp();

            // coalesced spike write-out
            for (int k = 0; k < cnt; ++k) {
                float* op       = out + (size_t)(g_row0 + k) * T_STEPS;
                const float* ip = ish_w + k * SM_STRIDE;
                #pragma unroll
                for (int q = 0; q < 4; ++q) {
                    const int t = lane + 32 * q;
                    if (t < T_STEPS) op[t] = ip[t];
                }
            }
            __syncwarp();
        }
    }
}

} // namespace

extern "C" void kernel_launch(void* const* d_in, const int* in_sizes, int n_in,
                              void* d_out, int out_size)
{
    const float* x = (const float*)d_in[0];
    const float* w = (const float*)d_in[1];
    float* out     = (float*)d_out;

    const int B = in_sizes[0] / ROW_FLOATS;   // 32768

    int num_sms = 148;
    cudaDeviceGetAttribute(&num_sms, cudaDevAttrMultiProcessorCount, 0);

    cudaFuncSetAttribute(exodus_kernel,
                         cudaFuncAttributeMaxDynamicSharedMemorySize, SMEM_BYTES);

    const int grid = 2 * num_sms;             // 2 blocks/SM, single persistent wave
    exodus_kernel<<<grid, THREADS, SMEM_BYTES>>>(x, w, out, B);
}

// round 8
// speedup vs baseline: 1.0546x; 1.0546x over previous
#include <cuda_runtime.h>
#include <cstdint>

// ExodusNet: per-timestep dense (32 -> 1), ExpLeak scan, LIF scan with
// SingleSpike + MembraneSubtract.  x: (B, 32, 100) fp32 (t innermost),
// w: (32) fp32, out: (B, 100) fp32 of 0/1 spikes.
//
// R8: identical per-warp structure to the 70.1us R6 kernel (2-stage
// cp.async.bulk ring, 4 rows per warp, bitwise-identical FMA/scan order).
// Block shrunk 4 warps -> 2 warps (THREADS 128 -> 64, BPB 16 -> 8):
// smem/block ~55KB -> 4 blocks/SM co-resident (vs 2), so any block's
// scan/writeout/launch bubble is covered by 3 streaming neighbors.

namespace {

constexpr int T_STEPS    = 100;
constexpr int F_DIM      = 32;
constexpr int ROW_FLOATS = F_DIM * T_STEPS;        // 3200 floats per row
constexpr int CHUNK      = ROW_FLOATS * 4;         // 12800 bytes per row
constexpr int THREADS    = 64;                     // 2 warps
constexpr int NWARP      = THREADS / 32;           // 2
constexpr int BPB        = 8;                      // batch rows per block
constexpr int B_PER_WARP = BPB / NWARP;            // 4 (same as R6)
constexpr int NSTAGE     = 2;                      // ring depth per warp
constexpr int SM_STRIDE  = 101;                    // conflict-free scan reads

// dynamic smem layout (bytes)
constexpr int WSH_OFF  = 0;                                    // 32 floats
constexpr int MBAR_OFF = 128;                                  // NWARP*NSTAGE*8
constexpr int ISH_OFF  = 192;                                  // BPB*SM_STRIDE floats
constexpr int ISH_BYTES = BPB * SM_STRIDE * 4;                 // 3232
constexpr int RING_OFF  = ISH_OFF + ((ISH_BYTES + 15) & ~15);  // 16B aligned
constexpr int SMEM_BYTES = RING_OFF + NWARP * NSTAGE * CHUNK;  // ~54.6 KB

__device__ __forceinline__ float alpha_f() { return (float)0.9048374180359595; }
__device__ __forceinline__ float one_m_a() { return (float)(1.0 - 0.9048374180359595); }

__device__ __forceinline__ uint32_t smem_u32(const void* p) {
    uint32_t a;
    asm("{ .reg .u64 t; cvta.to.shared.u64 t, %1; cvt.u32.u64 %0, t; }"
        : "=r"(a) : "l"(p));
    return a;
}
__device__ __forceinline__ void mbar_init(uint32_t mbar, uint32_t cnt) {
    asm volatile("mbarrier.init.shared.b64 [%0], %1;" :: "r"(mbar), "r"(cnt) : "memory");
}
__device__ __forceinline__ void mbar_expect_tx(uint32_t mbar, uint32_t bytes) {
    asm volatile("mbarrier.arrive.expect_tx.shared.b64 _, [%0], %1;"
                 :: "r"(mbar), "r"(bytes) : "memory");
}
__device__ __forceinline__ void bulk_copy_g2s(uint32_t dst_smem, const void* src_gmem,
                                              uint32_t bytes, uint32_t mbar) {
    asm volatile(
        "cp.async.bulk.shared::cluster.global.mbarrier::complete_tx::bytes "
        "[%0], [%1], %2, [%3];"
        :: "r"(dst_smem), "l"(src_gmem), "r"(bytes), "r"(mbar) : "memory");
}
__device__ __forceinline__ void mbar_wait_parity(uint32_t mbar, uint32_t parity) {
    asm volatile(
        "{\n\t"
        ".reg .pred P1;\n\t"
        "WAIT_LOOP_%=:\n\t"
        "mbarrier.try_wait.parity.acquire.cta.shared::cta.b64 P1, [%0], %1, 0x989680;\n\t"
        "@P1 bra.uni WAIT_DONE_%=;\n\t"
        "bra.uni WAIT_LOOP_%=;\n\t"
        "WAIT_DONE_%=:\n\t"
        "}"
        :: "r"(mbar), "r"(parity) : "memory");
}

__global__ __launch_bounds__(THREADS)
void exodus_kernel(const float* __restrict__ x,
                   const float* __restrict__ w,
                   float* __restrict__ out,
                   int B)
{
    extern __shared__ __align__(16) unsigned char smem_raw[];
    float* wsh = reinterpret_cast<float*>(smem_raw + WSH_OFF);
    float* ish = reinterpret_cast<float*>(smem_raw + ISH_OFF);

    const uint32_t smem_base = smem_u32(smem_raw);
    const int tid  = threadIdx.x;
    const int warp = tid >> 5;
    const int lane = tid & 31;
    const int b0   = blockIdx.x * BPB;

    if (tid < F_DIM) wsh[tid] = w[tid];
    if (tid == 0) {
        #pragma unroll
        for (int m = 0; m < NWARP * NSTAGE; ++m)
            mbar_init(smem_base + MBAR_OFF + m * 8, 1);
    }
    __syncthreads();

    // ---------------- Phase 1: TMA-streamed weighted currents ------------------
    const int      wb_base   = b0 + warp * B_PER_WARP;          // warp's first b
    const uint32_t ring_base = smem_base + RING_OFF + warp * (NSTAGE * CHUNK);
    const uint32_t mbar_base = smem_base + MBAR_OFF + warp * (NSTAGE * 8);

    // prologue: fill both stages
    if (lane == 0) {
        #pragma unroll
        for (int s = 0; s < NSTAGE; ++s) {
            const int b = wb_base + s;
            if (b < B) {
                mbar_expect_tx(mbar_base + s * 8, CHUNK);
                bulk_copy_g2s(ring_base + s * CHUNK, x + (size_t)b * ROW_FLOATS,
                              CHUNK, mbar_base + s * 8);
            }
        }
    }

    #pragma unroll
    for (int i = 0; i < B_PER_WARP; ++i) {
        const int b = wb_base + i;
        if (b >= B) break;
        const int s  = i & 1;
        const int ph = (i >> 1) & 1;
        mbar_wait_parity(mbar_base + s * 8, (uint32_t)ph);

        if (lane < 25) {
            const float* stage =
                reinterpret_cast<const float*>(smem_raw + RING_OFF +
                                               warp * (NSTAGE * CHUNK) + s * CHUNK);
            const float* base = stage + 4 * lane;
            float4 acc = make_float4(0.f, 0.f, 0.f, 0.f);
            #pragma unroll
            for (int f = 0; f < F_DIM; ++f) {
                const float4 xa = *reinterpret_cast<const float4*>(base + f * T_STEPS);
                const float wf = wsh[f];
                acc.x = fmaf(xa.x, wf, acc.x);
                acc.y = fmaf(xa.y, wf, acc.y);
                acc.z = fmaf(xa.z, wf, acc.z);
                acc.w = fmaf(xa.w, wf, acc.w);
            }
            float* ip = ish + (warp * B_PER_WARP + i) * SM_STRIDE + 4 * lane;
            ip[0] = acc.x;
            ip[1] = acc.y;
            ip[2] = acc.z;
            ip[3] = acc.w;
        }
        __syncwarp();   // all lanes done reading stage s before reissue

        const int nxt = i + NSTAGE;
        if (nxt < B_PER_WARP && lane == 0) {
            const int nb = wb_base + nxt;
            if (nb < B) {
                mbar_expect_tx(mbar_base + s * 8, CHUNK);
                bulk_copy_g2s(ring_base + s * CHUNK, x + (size_t)nb * ROW_FLOATS,
                              CHUNK, mbar_base + s * 8);
            }
        }
    }
    __syncthreads();

    // ---------------- Phase 2: sequential scans, one thread per b --------------
    if (tid < BPB && (b0 + tid) < B) {
        float* ip = ish + tid * SM_STRIDE;
        float syn = 0.f, v = 0.f;
        #pragma unroll 4
        for (int t = 0; t < T_STEPS; ++t) {
            const float i = ip[t];
            syn = fmaf(alpha_f(), syn, i);
            v   = fmaf(alpha_f(), v, one_m_a() * syn);
            const float s = (v >= 1.0f) ? 1.0f : 0.0f;
            v -= s;
            ip[t] = s;
        }
    }
    __syncthreads();

    // ---------------- Phase 3: coalesced spike write-out -----------------------
    {
        const int bl_begin = warp * B_PER_WARP;
        for (int bl = bl_begin; bl < bl_begin + B_PER_WARP; ++bl) {
            const int b = b0 + bl;
            if (b >= B) break;
            float* op       = out + (size_t)b * T_STEPS;
            const float* ip = ish + bl * SM_STRIDE;
            #pragma unroll
            for (int j = 0; j < 4; ++j) {
                const int t = lane + 32 * j;
                if (t < T_STEPS) op[t] = ip[t];
            }
        }
    }
}

} // namespace

extern "C" void kernel_launch(void* const* d_in, const int* in_sizes, int n_in,
                              void* d_out, int out_size)
{
    const float* x = (const float*)d_in[0];
    const float* w = (const float*)d_in[1];
    float* out     = (float*)d_out;

    const int B = in_sizes[0] / ROW_FLOATS;   // 32768

    cudaFuncSetAttribute(exodus_kernel,
                         cudaFuncAttributeMaxDynamicSharedMemorySize, SMEM_BYTES);

    const int grid = (B + BPB - 1) / BPB;     // 4096
    exodus_kernel<<<grid, THREADS, SMEM_BYTES>>>(x, w, out, B);
}

// round 9
// speedup vs baseline: 1.0579x; 1.0032x over previous
#include <cuda_runtime.h>
#include <cstdint>

// ExodusNet: per-timestep dense (32 -> 1), ExpLeak scan, LIF scan with
// SingleSpike + MembraneSubtract.  x: (B, 32, 100) fp32 (t innermost),
// w: (32) fp32, out: (B, 100) fp32 of 0/1 spikes.
//
// R9: per-warp code identical to the 70.1us R6 kernel (2-stage
// cp.async.bulk ring, bitwise-identical FMA/scan order), but:
//   - 8 rows per warp (one long streaming burst, half the blocks/launches)
//   - fully warp-autonomous: scan (8 lanes) + writeout per warp, no
//     __syncthreads after init -> no inter-warp convoying
//   - grid 2048, ~3 blocks/SM resident -> neighbor blocks cover each
//     warp's scan/writeout tail.

namespace {

constexpr int T_STEPS    = 100;
constexpr int F_DIM      = 32;
constexpr int ROW_FLOATS = F_DIM * T_STEPS;        // 3200 floats per row
constexpr int CHUNK      = ROW_FLOATS * 4;         // 12800 bytes per row
constexpr int THREADS    = 64;                     // 2 warps
constexpr int NWARP      = THREADS / 32;           // 2
constexpr int B_PER_WARP = 8;
constexpr int BPB        = NWARP * B_PER_WARP;     // 16
constexpr int NSTAGE     = 2;                      // ring depth per warp
constexpr int SM_STRIDE  = 101;                    // conflict-free scan reads

// dynamic smem layout (bytes)
constexpr int WSH_OFF   = 0;                                   // 32 floats
constexpr int MBAR_OFF  = 128;                                 // NWARP*NSTAGE*8
constexpr int ISH_OFF   = 192;                                 // BPB*SM_STRIDE floats
constexpr int ISH_BYTES = BPB * SM_STRIDE * 4;                 // 6464
constexpr int RING_OFF  = ISH_OFF + ((ISH_BYTES + 15) & ~15);  // 16B aligned
constexpr int SMEM_BYTES = RING_OFF + NWARP * NSTAGE * CHUNK;  // ~57.9 KB

__device__ __forceinline__ float alpha_f() { return (float)0.9048374180359595; }
__device__ __forceinline__ float one_m_a() { return (float)(1.0 - 0.9048374180359595); }

__device__ __forceinline__ uint32_t smem_u32(const void* p) {
    uint32_t a;
    asm("{ .reg .u64 t; cvta.to.shared.u64 t, %1; cvt.u32.u64 %0, t; }"
        : "=r"(a) : "l"(p));
    return a;
}
__device__ __forceinline__ void mbar_init(uint32_t mbar, uint32_t cnt) {
    asm volatile("mbarrier.init.shared.b64 [%0], %1;" :: "r"(mbar), "r"(cnt) : "memory");
}
__device__ __forceinline__ void mbar_expect_tx(uint32_t mbar, uint32_t bytes) {
    asm volatile("mbarrier.arrive.expect_tx.shared.b64 _, [%0], %1;"
                 :: "r"(mbar), "r"(bytes) : "memory");
}
__device__ __forceinline__ void bulk_copy_g2s(uint32_t dst_smem, const void* src_gmem,
                                              uint32_t bytes, uint32_t mbar) {
    asm volatile(
        "cp.async.bulk.shared::cluster.global.mbarrier::complete_tx::bytes "
        "[%0], [%1], %2, [%3];"
        :: "r"(dst_smem), "l"(src_gmem), "r"(bytes), "r"(mbar) : "memory");
}
__device__ __forceinline__ void mbar_wait_parity(uint32_t mbar, uint32_t parity) {
    asm volatile(
        "{\n\t"
        ".reg .pred P1;\n\t"
        "WAIT_LOOP_%=:\n\t"
        "mbarrier.try_wait.parity.acquire.cta.shared::cta.b64 P1, [%0], %1, 0x989680;\n\t"
        "@P1 bra.uni WAIT_DONE_%=;\n\t"
        "bra.uni WAIT_LOOP_%=;\n\t"
        "WAIT_DONE_%=:\n\t"
        "}"
        :: "r"(mbar), "r"(parity) : "memory");
}

__global__ __launch_bounds__(THREADS)
void exodus_kernel(const float* __restrict__ x,
                   const float* __restrict__ w,
                   float* __restrict__ out,
                   int B)
{
    extern __shared__ __align__(16) unsigned char smem_raw[];
    float* wsh = reinterpret_cast<float*>(smem_raw + WSH_OFF);
    float* ish = reinterpret_cast<float*>(smem_raw + ISH_OFF);

    const uint32_t smem_base = smem_u32(smem_raw);
    const int tid  = threadIdx.x;
    const int warp = tid >> 5;
    const int lane = tid & 31;
    const int b0   = blockIdx.x * BPB;

    if (tid < F_DIM) wsh[tid] = w[tid];
    if (tid == 0) {
        #pragma unroll
        for (int m = 0; m < NWARP * NSTAGE; ++m)
            mbar_init(smem_base + MBAR_OFF + m * 8, 1);
    }
    __syncthreads();   // only block-wide barrier (init + wsh visibility)

    // ---------------- Phase 1: TMA-streamed weighted currents ------------------
    const int      wb_base   = b0 + warp * B_PER_WARP;          // warp's first b
    const uint32_t ring_base = smem_base + RING_OFF + warp * (NSTAGE * CHUNK);
    const uint32_t mbar_base = smem_base + MBAR_OFF + warp * (NSTAGE * 8);
    float* ish_w = ish + warp * (B_PER_WARP * SM_STRIDE);

    // prologue: fill both stages
    if (lane == 0) {
        #pragma unroll
        for (int s = 0; s < NSTAGE; ++s) {
            const int b = wb_base + s;
            if (b < B) {
                mbar_expect_tx(mbar_base + s * 8, CHUNK);
                bulk_copy_g2s(ring_base + s * CHUNK, x + (size_t)b * ROW_FLOATS,
                              CHUNK, mbar_base + s * 8);
            }
        }
    }

    #pragma unroll
    for (int i = 0; i < B_PER_WARP; ++i) {
        const int b = wb_base + i;
        if (b >= B) break;
        const int s  = i & 1;
        const int ph = (i >> 1) & 1;
        mbar_wait_parity(mbar_base + s * 8, (uint32_t)ph);

        if (lane < 25) {
            const float* stage =
                reinterpret_cast<const float*>(smem_raw + RING_OFF +
                                               warp * (NSTAGE * CHUNK) + s * CHUNK);
            const float* base = stage + 4 * lane;
            float4 acc = make_float4(0.f, 0.f, 0.f, 0.f);
            #pragma unroll
            for (int f = 0; f < F_DIM; ++f) {
                const float4 xa = *reinterpret_cast<const float4*>(base + f * T_STEPS);
                const float wf = wsh[f];
                acc.x = fmaf(xa.x, wf, acc.x);
                acc.y = fmaf(xa.y, wf, acc.y);
                acc.z = fmaf(xa.z, wf, acc.z);
                acc.w = fmaf(xa.w, wf, acc.w);
            }
            float* ip = ish_w + i * SM_STRIDE + 4 * lane;
            ip[0] = acc.x;
            ip[1] = acc.y;
            ip[2] = acc.z;
            ip[3] = acc.w;
        }
        __syncwarp();   // all lanes done reading stage s before reissue

        const int nxt = i + NSTAGE;
        if (nxt < B_PER_WARP && lane == 0) {
            const int nb = wb_base + nxt;
            if (nb < B) {
                mbar_expect_tx(mbar_base + s * 8, CHUNK);
                bulk_copy_g2s(ring_base + s * CHUNK, x + (size_t)nb * ROW_FLOATS,
                              CHUNK, mbar_base + s * 8);
            }
        }
    }
    __syncwarp();

    // ---------------- Phase 2: sequential scans, warp-local (8 lanes) ----------
    // syn[t] = a*syn[t-1] + i[t]
    // v[t]   = a*v[t-1] + (1-a)*syn[t];  s = (v >= 1);  v -= s
    if (lane < B_PER_WARP && (wb_base + lane) < B) {
        float* ip = ish_w + lane * SM_STRIDE;
        float syn = 0.f, v = 0.f;
        #pragma unroll 4
        for (int t = 0; t < T_STEPS; ++t) {
            const float i = ip[t];
            syn = fmaf(alpha_f(), syn, i);
            v   = fmaf(alpha_f(), v, one_m_a() * syn);
            const float s = (v >= 1.0f) ? 1.0f : 0.0f;
            v -= s;
            ip[t] = s;
        }
    }
    __syncwarp();

    // ---------------- Phase 3: coalesced spike write-out (warp-local) ----------
    for (int k = 0; k < B_PER_WARP; ++k) {
        const int b = wb_base + k;
        if (b >= B) break;
        float* op       = out + (size_t)b * T_STEPS;
        const float* ip = ish_w + k * SM_STRIDE;
        #pragma unroll
        for (int j = 0; j < 4; ++j) {
            const int t = lane + 32 * j;
            if (t < T_STEPS) op[t] = ip[t];
        }
    }
}

} // namespace

extern "C" void kernel_launch(void* const* d_in, const int* in_sizes, int n_in,
                              void* d_out, int out_size)
{
    const float* x = (const float*)d_in[0];
    const float* w = (const float*)d_in[1];
    float* out     = (float*)d_out;

    const int B = in_sizes[0] / ROW_FLOATS;   // 32768

    cudaFuncSetAttribute(exodus_kernel,
                         cudaFuncAttributeMaxDynamicSharedMemorySize, SMEM_BYTES);

    const int grid = (B + BPB - 1) / BPB;     // 2048
    exodus_kernel<<<grid, THREADS, SMEM_BYTES>>>(x, w, out, B);
}